// round 8
// baseline (speedup 1.0000x reference)
#include <cuda_runtime.h>
#include <float.h>

// Problem constants
#define HH 512
#define WW 512
#define MBS 8          // macroblock size
#define PR 8           // search range
#define NBR 64
#define NBC 64
#define NPAIR 14       // frame pairs actually used (motion[:-1])
#define NBATCH 4
#define CROPX 17
#define OUTD 478       // 512 - 2*17
#define LARGEC 65537.0f
#define MAX_STEPS 16

// Per-group window: 24 rows x 24 cols at stride SWG=38 (== 6 mod 32).
// Candidate bank deltas mdy*6+mdx are all distinct mod 32; window size
// 912 words == 16 mod 32 gives even/odd groups disjoint bank sets ->
// the warp's 28 active window LDS lanes are fully conflict-free.
#define SWG 38
#define WSZ (24 * SWG)   // 912 words per group window

// Motion vectors scratch: (dy, dx) per block. Static device global (no allocs).
__device__ int2 g_motion[NBATCH * NPAIR * NBR * NBC];

// LDSP points as (dx, dy) matching reference ordering; cost uses (y+dy, x+dx).
__constant__ int c_ldsp_dx[9] = { 0, -1, 1, -2, 0, 2, -1, 1, 0 };
__constant__ int c_ldsp_dy[9] = { -2, -1, -1, 0, 0, 0, 1, 1, 2 };
__constant__ int c_sdsp_dx[5] = { 0, -1, 0, 1, 0 };
__constant__ int c_sdsp_dy[5] = { -1, 0, 0, 0, 1 };

// One CTA: 8 macroblocks. 128 threads = 8 groups of 16 lanes.
// Lanes 0-8: LDSP candidates; lanes 9-13: speculative SDSP at the center
// (valid when the loop exits with pt==4, which is the only non-fallback exit).
// SAD accumulation replicates XLA GPU's row-reduction association:
//   pacc[t] = |d|[t] + |d|[t+32], then tree offsets 16,8,4,2,1 (bit-exact argmin).
// Block operand read from smem via float2 broadcast (confirmed fastest).
__global__ __launch_bounds__(128) void motion_kernel(const float* __restrict__ x) {
    __shared__ float swin[8 * WSZ];   // 8 per-group windows, bank-engineered
    __shared__ float sblk[8 * 64];    // current-frame blocks for this tile

    const int jt  = blockIdx.x;              // col tile 0..7
    const int bi  = blockIdx.y;              // block row 0..63
    const int bp_ = blockIdx.z;              // b*NPAIR + p, 0..55
    const int b   = bp_ / NPAIR;
    const int p   = bp_ % NPAIR;

    const float* imgI = x + (size_t)(b * 16 + p) * HH * WW;       // reference (t-1)
    const float* imgP = imgI + (size_t)HH * WW;                   // current  (t)

    const int i  = bi * MBS;
    const int j0 = jt * 64;
    const int tid = threadIdx.x;

    // Fill per-group windows: rows [i-8,i+16), cols [jg-8,jg+16), clamped.
    // Clamped cells are only ever read by invalid (predicated-off) candidates.
    for (int e = tid; e < 8 * 576; e += 128) {
        int gg  = e / 576;
        int rem = e - gg * 576;
        int r   = rem / 24;
        int c   = rem - r * 24;
        int gr = i - 8 + r;           gr = gr < 0 ? 0 : (gr > HH - 1 ? HH - 1 : gr);
        int gc = j0 + gg * 8 - 8 + c; gc = gc < 0 ? 0 : (gc > WW - 1 ? WW - 1 : gc);
        swin[gg * WSZ + r * SWG + c] = imgI[gr * WW + gc];
    }
    for (int t = tid; t < 8 * 64; t += 128) {
        int r = t >> 6, c = t & 63;
        sblk[t] = imgP[(i + r) * WW + (j0 + c)];
    }
    __syncthreads();

    const int g  = tid >> 4;       // group (macroblock) 0..7
    const int lg = tid & 15;       // lane in group
    const unsigned gmask = 0xFFFFu << (tid & 16);
    const int j = j0 + g * 8;
    const float* bb = sblk + g * 8;
    const float* wg = swin + g * WSZ;

    // SAD mean, XLA association. Block operand via aligned float2 broadcast.
    auto evalc = [&](int cy, int cx) -> float {
        const float* wp = wg + (cy - i + 8) * SWG + (cx - j + 8);
        float pacc[32];
#pragma unroll
        for (int tp = 0; tp < 16; tp++) {
            int t  = tp * 2;
            int r0 = t >> 3, c0_ = t & 7;   // element t   (pairs never cross rows)
            int r1 = r0 + 4;                // element t+32
            float2 b0 = *(const float2*)(bb + r0 * 64 + c0_);
            float2 b1 = *(const float2*)(bb + r1 * 64 + c0_);
            float w00 = wp[r0 * SWG + c0_], w01 = wp[r0 * SWG + c0_ + 1];
            float w10 = wp[r1 * SWG + c0_], w11 = wp[r1 * SWG + c0_ + 1];
            pacc[t]     = fabsf(b0.x - w00) + fabsf(b1.x - w10);
            pacc[t + 1] = fabsf(b0.y - w01) + fabsf(b1.y - w11);
        }
#pragma unroll
        for (int off = 16; off >= 1; off >>= 1)
#pragma unroll
            for (int t = 0; t < 16; t++)
                if (t < off) pacc[t] = pacc[t] + pacc[t + off];
        return pacc[0] * 0.015625f;
    };

    auto costat = [&](int cy, int cx) -> float {
        bool valid = (cy >= 0) && (cy + MBS <= HH) && (cx >= 0) && (cx + MBS <= WW)
                   && (cy - i <= PR) && (i - cy <= PR) && (cx - j <= PR) && (j - cx <= PR);
        float cst = LARGEC;
        if (valid) cst = evalc(cy, cx);
        return cst;
    };

    // Lane role: 0-8 LDSP, 9-13 SDSP(lg-9), 14-15 dup SDSP center (unused).
    const bool isldsp = (lg < 9);
    const int  sdi    = (lg >= 9 && lg < 14) ? (lg - 9) : 2;
    const int  mdy    = isldsp ? c_ldsp_dy[lg] : c_sdsp_dy[sdi];
    const int  mdx    = isldsp ? c_ldsp_dx[lg] : c_sdsp_dx[sdi];

    int y = i, xx = j;
    float my_sdsp = FLT_MAX;
    bool have_sdsp = false;

    for (int k = 0; k < MAX_STEPS; k++) {
        float cost = costat(y + mdy, xx + mdx);
        if (lg >= 9) my_sdsp = cost;

        if (k == 0) {
            // Reference's standalone c0 check == this iteration's lane 4 cost.
            float ctr = __shfl_sync(gmask, cost, 4, 16);
            if (ctr == 0.0f) { have_sdsp = true; break; }
        }

        // LDSP argmin: lexicographic (cost, idx) == jnp.argmin first-index
        float cc = isldsp ? cost : FLT_MAX;
        int  idx = isldsp ? lg : 15;
#pragma unroll
        for (int off = 8; off >= 1; off >>= 1) {
            float oc = __shfl_xor_sync(gmask, cc, off, 16);
            int   oi = __shfl_xor_sync(gmask, idx, off, 16);
            if (oc < cc || (oc == cc && oi < idx)) { cc = oc; idx = oi; }
        }
        if (idx == 4) { have_sdsp = true; break; }   // center: speculative SDSP valid
        y  += c_ldsp_dy[idx];
        xx += c_ldsp_dx[idx];
    }

    // SDSP refinement: use speculative costs, or (rare: MAX_STEPS exit) recompute.
    {
        float sv = FLT_MAX;
        int   si = 15;
        if (have_sdsp) {
            if (lg >= 9 && lg < 14) { sv = my_sdsp; si = lg - 9; }
        } else {
            if (lg < 5) { sv = costat(y + c_sdsp_dy[lg], xx + c_sdsp_dx[lg]); si = lg; }
        }
#pragma unroll
        for (int off = 8; off >= 1; off >>= 1) {
            float oc = __shfl_xor_sync(gmask, sv, off, 16);
            int   oi = __shfl_xor_sync(gmask, si, off, 16);
            if (oc < sv || (oc == sv && oi < si)) { sv = oc; si = oi; }
        }
        y  += c_sdsp_dy[si];
        xx += c_sdsp_dx[si];
    }

    if (lg == 0) {
        g_motion[(bp_ * NBR + bi) * NBC + (jt * 8 + g)] = make_int2(y - i, xx - j);
    }
}

// Output: first half = target (crop of frame f+2), second half = pred
// (motion-compensated warp of frame f+1 through g_motion, cropped).
// 4 rows per thread -> 8+ independent loads in flight (L2-latency bound).
__global__ void out_kernel(const float* __restrict__ x, float* __restrict__ out) {
    int c = blockIdx.x * blockDim.x + threadIdx.x;
    if (c >= OUTD) return;
    int rb = blockIdx.y * 4;          // rows rb .. rb+3 (guarded; 478 = 4*119+2)
    int z  = blockIdx.z;              // b*NPAIR + f
    int b = z / NPAIR;
    int f = z - b * NPAIR;

    const float* base = x + (size_t)b * 16 * HH * WW;
    const float* tgt  = base + (size_t)(f + 2) * HH * WW;
    const float* ref  = base + (size_t)(f + 1) * HH * WW;
    const size_t TOT = (size_t)NBATCH * NPAIR * OUTD * OUTD;
    const int2* mrow = &g_motion[(b * NPAIR + f) * NBR * NBC];

    int C = CROPX + c;
    int cb = C >> 3;

    float t_[4], p_[4];
    int nr = (OUTD - rb) < 4 ? (OUTD - rb) : 4;

#pragma unroll
    for (int u = 0; u < 4; u++) {
        if (u < nr) {
            int R = CROPX + rb + u;
            t_[u] = tgt[(size_t)R * WW + C];
            int2 m = mrow[(R >> 3) * NBC + cb];
            p_[u] = ref[(size_t)(R + m.x) * WW + (C + m.y)];
        }
    }

    size_t o = ((size_t)z * OUTD + rb) * OUTD + c;
#pragma unroll
    for (int u = 0; u < 4; u++) {
        if (u < nr) {
            out[o + (size_t)u * OUTD] = t_[u];
            out[TOT + o + (size_t)u * OUTD] = p_[u];
        }
    }
}

extern "C" void kernel_launch(void* const* d_in, const int* in_sizes, int n_in,
                              void* d_out, int out_size) {
    const float* x = (const float*)d_in[0];
    float* out = (float*)d_out;

    dim3 gm(8, 64, NBATCH * NPAIR);   // 8 col-tiles x 64 block-rows x (4*14)
    motion_kernel<<<gm, 128>>>(x);

    dim3 go((OUTD + 255) / 256, (OUTD + 3) / 4, NBATCH * NPAIR);
    out_kernel<<<go, 256>>>(x, out);
}

// round 9
// speedup vs baseline: 1.0960x; 1.0960x over previous
#include <cuda_runtime.h>
#include <float.h>

// Problem constants
#define HH 512
#define WW 512
#define MBS 8          // macroblock size
#define PR 8           // search range
#define NBR 64
#define NBC 64
#define NPAIR 14       // frame pairs actually used (motion[:-1])
#define NBATCH 4
#define CROPX 17
#define OUTD 478       // 512 - 2*17
#define LARGEC 65537.0f
#define MAX_STEPS 16
#define SW 84          // padded smem window stride (cols)

// Motion vectors scratch: (dy, dx) per block. Static device global (no allocs).
__device__ int2 g_motion[NBATCH * NPAIR * NBR * NBC];

// LDSP points as (dx, dy) matching reference ordering; cost uses (y+dy, x+dx).
__constant__ int c_ldsp_dx[9] = { 0, -1, 1, -2, 0, 2, -1, 1, 0 };
__constant__ int c_ldsp_dy[9] = { -2, -1, -1, 0, 0, 0, 1, 1, 2 };
__constant__ int c_sdsp_dx[5] = { 0, -1, 0, 1, 0 };
__constant__ int c_sdsp_dy[5] = { -1, 0, 0, 0, 1 };

// Exact a+b via FFMA with immediate 1.0 multiplier (single rounding, bit-equal
// to FADD) — hits the rt=1 FFMA-imm form vs FADD's rt=2 on the fma pipe.
__device__ __forceinline__ float addx(float a, float b) {
    float d;
    asm("fma.rn.f32 %0, %1, 0f3F800000, %2;" : "=f"(d) : "f"(a), "f"(b));
    return d;
}

// One CTA: 8 macroblocks of one block-row segment. 128 threads = 8 groups of 16.
// Per group: lanes 0-8 evaluate the 9 LDSP candidates; lanes 9-13 speculatively
// evaluate the 5 SDSP candidates at the SAME center (valid when the loop exits
// with pt==4). SAD accumulation replicates XLA GPU's row-reduction association:
//   pacc[t] = |d|[t] + |d|[t+32], then tree offsets 16,8,4,2,1 (bit-exact argmin).
// Window kept in TWO parity copies (swin, swin1 = shifted one column) so every
// lane's pairwise window read is an aligned LDS.64 regardless of candidate x
// parity: window LDS issue count halves (LDS issue rate is the binding resource).
__global__ __launch_bounds__(128) void motion_kernel(const float* __restrict__ x) {
    __shared__ __align__(16) float swin [24 * SW];  // window rows [i-8,i+16), cols [j0-8,j0+72)
    __shared__ __align__(16) float swin1[24 * SW];  // same, shifted: swin1[r][c] = win[r][c+1]
    __shared__ __align__(16) float sblk [8 * 64];   // current-frame blocks for this tile

    const int jt  = blockIdx.x;              // col tile 0..7
    const int bi  = blockIdx.y;              // block row 0..63
    const int bp_ = blockIdx.z;              // b*NPAIR + p, 0..55
    const int b   = bp_ / NPAIR;
    const int p   = bp_ % NPAIR;

    const float* imgI = x + (size_t)(b * 16 + p) * HH * WW;       // reference (t-1)
    const float* imgP = imgI + (size_t)HH * WW;                   // current  (t)

    const int i  = bi * MBS;
    const int j0 = jt * 64;
    const int tid = threadIdx.x;

    // Cooperative loads (clamped; out-of-range rows/cols only back invalid candidates)
    for (int t = tid; t < 24 * 80; t += 128) {
        int r = t / 80, c = t - (t / 80) * 80;
        int gr = i - 8 + r;  gr = gr < 0 ? 0 : (gr > HH - 1 ? HH - 1 : gr);
        int gc = j0 - 8 + c; gc = gc < 0 ? 0 : (gc > WW - 1 ? WW - 1 : gc);
        float v = imgI[gr * WW + gc];
        swin[r * SW + c] = v;
        if (c > 0) swin1[r * SW + (c - 1)] = v;
    }
    for (int t = tid; t < 8 * 64; t += 128) {
        int r = t >> 6, c = t & 63;
        sblk[t] = imgP[(i + r) * WW + (j0 + c)];
    }
    __syncthreads();

    const int g  = tid >> 4;       // group (macroblock) 0..7
    const int lg = tid & 15;       // lane in group
    const unsigned gmask = 0xFFFFu << (tid & 16);
    const int j = j0 + g * 8;
    const float* bb = sblk + g * 8;

    // SAD mean, XLA association. Window reads are aligned float2 via the
    // parity-selected copy; block reads are float2 broadcast.
    auto evalc = [&](int cy, int cx) -> float {
        const int row = cy - i + 8;
        const int o   = cx - j0 + 8;
        const float* wp = (o & 1) ? (swin1 + row * SW + (o - 1))
                                  : (swin  + row * SW + o);
        float pacc[32];
#pragma unroll
        for (int tp = 0; tp < 16; tp++) {
            int t  = tp * 2;
            int r0 = t >> 3, c0_ = t & 7;   // element t   (pairs never cross rows)
            int r1 = r0 + 4;                // element t+32
            float2 b0 = *(const float2*)(bb + r0 * 64 + c0_);
            float2 b1 = *(const float2*)(bb + r1 * 64 + c0_);
            float2 w0 = *(const float2*)(wp + r0 * SW + c0_);
            float2 w1 = *(const float2*)(wp + r1 * SW + c0_);
            pacc[t]     = fabsf(b0.x - w0.x) + fabsf(b1.x - w1.x);
            pacc[t + 1] = fabsf(b0.y - w0.y) + fabsf(b1.y - w1.y);
        }
#pragma unroll
        for (int off = 16; off >= 1; off >>= 1)
#pragma unroll
            for (int t = 0; t < 16; t++)
                if (t < off) pacc[t] = addx(pacc[t], pacc[t + off]);
        return pacc[0] * 0.015625f;
    };

    auto costat = [&](int cy, int cx) -> float {
        bool valid = (cy >= 0) && (cy + MBS <= HH) && (cx >= 0) && (cx + MBS <= WW)
                   && (cy - i <= PR) && (i - cy <= PR) && (cx - j <= PR) && (j - cx <= PR);
        float cst = LARGEC;
        if (valid) cst = evalc(cy, cx);
        return cst;
    };

    // Lane role: 0-8 LDSP, 9-13 SDSP(lg-9), 14-15 dup SDSP center (unused).
    const bool isldsp = (lg < 9);
    const int  sdi    = (lg >= 9 && lg < 14) ? (lg - 9) : 2;
    const int  mdy    = isldsp ? c_ldsp_dy[lg] : c_sdsp_dy[sdi];
    const int  mdx    = isldsp ? c_ldsp_dx[lg] : c_sdsp_dx[sdi];

    int y = i, xx = j;
    float my_sdsp = FLT_MAX;
    bool have_sdsp = false;

    for (int k = 0; k < MAX_STEPS; k++) {
        float cost = costat(y + mdy, xx + mdx);
        if (lg >= 9) my_sdsp = cost;

        if (k == 0) {
            // Reference's standalone c0 check == this iteration's lane 4 cost.
            float ctr = __shfl_sync(gmask, cost, 4, 16);
            if (ctr == 0.0f) { have_sdsp = true; break; }
        }

        // LDSP argmin: lexicographic (cost, idx) == jnp.argmin first-index
        float cc = isldsp ? cost : FLT_MAX;
        int  idx = isldsp ? lg : 15;
#pragma unroll
        for (int off = 8; off >= 1; off >>= 1) {
            float oc = __shfl_xor_sync(gmask, cc, off, 16);
            int   oi = __shfl_xor_sync(gmask, idx, off, 16);
            if (oc < cc || (oc == cc && oi < idx)) { cc = oc; idx = oi; }
        }
        if (idx == 4) { have_sdsp = true; break; }   // center: speculative SDSP valid
        y  += c_ldsp_dy[idx];
        xx += c_ldsp_dx[idx];
    }

    // SDSP refinement: use speculative costs, or (rare: MAX_STEPS exit) recompute.
    {
        float sv = FLT_MAX;
        int   si = 15;
        if (have_sdsp) {
            if (lg >= 9 && lg < 14) { sv = my_sdsp; si = lg - 9; }
        } else {
            if (lg < 5) { sv = costat(y + c_sdsp_dy[lg], xx + c_sdsp_dx[lg]); si = lg; }
        }
#pragma unroll
        for (int off = 8; off >= 1; off >>= 1) {
            float oc = __shfl_xor_sync(gmask, sv, off, 16);
            int   oi = __shfl_xor_sync(gmask, si, off, 16);
            if (oc < sv || (oc == sv && oi < si)) { sv = oc; si = oi; }
        }
        y  += c_sdsp_dy[si];
        xx += c_sdsp_dx[si];
    }

    if (lg == 0) {
        g_motion[(bp_ * NBR + bi) * NBC + (jt * 8 + g)] = make_int2(y - i, xx - j);
    }
}

// Output: first half = target (crop of frame f+2), second half = pred
// (motion-compensated warp of frame f+1 through g_motion, cropped).
// 4 rows per thread -> 8+ independent loads in flight (L2-latency bound).
__global__ void out_kernel(const float* __restrict__ x, float* __restrict__ out) {
    int c = blockIdx.x * blockDim.x + threadIdx.x;
    if (c >= OUTD) return;
    int rb = blockIdx.y * 4;          // rows rb .. rb+3 (guarded; 478 = 4*119+2)
    int z  = blockIdx.z;              // b*NPAIR + f
    int b = z / NPAIR;
    int f = z - b * NPAIR;

    const float* base = x + (size_t)b * 16 * HH * WW;
    const float* tgt  = base + (size_t)(f + 2) * HH * WW;
    const float* ref  = base + (size_t)(f + 1) * HH * WW;
    const size_t TOT = (size_t)NBATCH * NPAIR * OUTD * OUTD;
    const int2* mrow = &g_motion[(b * NPAIR + f) * NBR * NBC];

    int C = CROPX + c;
    int cb = C >> 3;

    float t_[4], p_[4];
    int nr = (OUTD - rb) < 4 ? (OUTD - rb) : 4;

#pragma unroll
    for (int u = 0; u < 4; u++) {
        if (u < nr) {
            int R = CROPX + rb + u;
            t_[u] = tgt[(size_t)R * WW + C];
            int2 m = mrow[(R >> 3) * NBC + cb];
            p_[u] = ref[(size_t)(R + m.x) * WW + (C + m.y)];
        }
    }

    size_t o = ((size_t)z * OUTD + rb) * OUTD + c;
#pragma unroll
    for (int u = 0; u < 4; u++) {
        if (u < nr) {
            out[o + (size_t)u * OUTD] = t_[u];
            out[TOT + o + (size_t)u * OUTD] = p_[u];
        }
    }
}

extern "C" void kernel_launch(void* const* d_in, const int* in_sizes, int n_in,
                              void* d_out, int out_size) {
    const float* x = (const float*)d_in[0];
    float* out = (float*)d_out;

    dim3 gm(8, 64, NBATCH * NPAIR);   // 8 col-tiles x 64 block-rows x (4*14)
    motion_kernel<<<gm, 128>>>(x);

    dim3 go((OUTD + 255) / 256, (OUTD + 3) / 4, NBATCH * NPAIR);
    out_kernel<<<go, 256>>>(x, out);
}